// round 13
// baseline (speedup 1.0000x reference)
#include <cuda_runtime.h>
#include <cuda_fp16.h>
#include <cstdint>

// ---------------------------------------------------------------------------
// CrossAttentionDecoder — single fused per-batch kernel.
//   prep_w : fp16 weights (Wq pre-scaled by 0.125)
//   fused  : per batch b (one CTA, warp = head):
//     P0  stage x[b] -> x_s fp16, l[b] masked rows -> l_s fp16 (once)
//     P1  q_h   = x @ Wq_h^T          (Wq streamed, C->A reg pack -> aq)
//     P2  qk    = q_h @ Wk_h  ; scores = qk @ l^T   (cs in regs)
//     P3  masked softmax -> s_s
//     P4  AL    = attn @ l    ; OV    += AL @ Wv_h^T (C->A pack, cov regs)
//     P5  cov -> ov_s (x_s reuse); out = OV @ Wo^T + bo
// No inter-kernel scratch tensors at all.
// ---------------------------------------------------------------------------

#define DIM 512
#define NLAT 128
#define NTOK 16
#define NB 1024

__device__ __half g_Wqh[DIM * DIM];   // 0.125 * Wq
__device__ __half g_Wkh[DIM * DIM];
__device__ __half g_Wvh[DIM * DIM];
__device__ __half g_Woh[DIM * DIM];

// smem layout (halves): x_s[16][520] | l_s[128][520] | s_s[128][136] | w_s[512][40]
#define XS_OFF 0
#define LS_OFF (16 * 520)
#define SS_OFF (LS_OFF + 128 * 520)
#define WS_OFF (SS_OFF + 128 * 136)
#define SMEM_H (WS_OFF + 512 * 40)          // 112768 halves = 225536 bytes
#define SMEM_B (SMEM_H * 2)

__device__ __forceinline__ uint32_t packh2(float a, float b) {
    __half2 h = __floats2half2_rn(a, b);
    return *reinterpret_cast<uint32_t*>(&h);
}
__device__ __forceinline__ uint2 pack4(float4 v) {
    return make_uint2(packh2(v.x, v.y), packh2(v.z, v.w));
}
__device__ __forceinline__ void mma_fp16(float* c, uint32_t a0, uint32_t a1,
                                         uint32_t a2, uint32_t a3,
                                         uint32_t b0, uint32_t b1) {
    asm volatile(
        "mma.sync.aligned.m16n8k16.row.col.f32.f16.f16.f32 "
        "{%0,%1,%2,%3}, {%4,%5,%6,%7}, {%8,%9}, {%0,%1,%2,%3};\n"
        : "+f"(c[0]), "+f"(c[1]), "+f"(c[2]), "+f"(c[3])
        : "r"(a0), "r"(a1), "r"(a2), "r"(a3), "r"(b0), "r"(b1));
}
__device__ __forceinline__ void ldsm_x4(uint32_t& r0, uint32_t& r1,
                                        uint32_t& r2, uint32_t& r3, uint32_t a) {
    asm volatile("ldmatrix.sync.aligned.m8n8.x4.shared.b16 {%0,%1,%2,%3}, [%4];"
        : "=r"(r0), "=r"(r1), "=r"(r2), "=r"(r3) : "r"(a));
}
__device__ __forceinline__ void ldsm_x4t(uint32_t& r0, uint32_t& r1,
                                         uint32_t& r2, uint32_t& r3, uint32_t a) {
    asm volatile("ldmatrix.sync.aligned.m8n8.x4.trans.shared.b16 {%0,%1,%2,%3}, [%4];"
        : "=r"(r0), "=r"(r1), "=r"(r2), "=r"(r3) : "r"(a));
}
__device__ __forceinline__ uint32_t sm_u32(const void* p) {
    return (uint32_t)__cvta_generic_to_shared(p);
}
__device__ __forceinline__ void cp16(uint32_t smem_dst, const void* gsrc) {
    asm volatile("cp.async.cg.shared.global [%0], [%1], 16;"
                 :: "r"(smem_dst), "l"(gsrc));
}
// pack two n8 C-groups (n16 span) into one m16k16 A-fragment set
__device__ __forceinline__ void packA(const float* clo, const float* chi,
                                      uint32_t& a0, uint32_t& a1,
                                      uint32_t& a2, uint32_t& a3) {
    a0 = packh2(clo[0], clo[1]);   // (g,   2t..2t+1)
    a1 = packh2(clo[2], clo[3]);   // (g+8, 2t..2t+1)
    a2 = packh2(chi[0], chi[1]);   // (g,   8+2t..)
    a3 = packh2(chi[2], chi[3]);   // (g+8, 8+2t..)
}

// ---------------------------------------------------------------------------
// prep: fp16 weight conversions (Wq scaled by 0.125). 262144 float4 total.
// ---------------------------------------------------------------------------
__global__ __launch_bounds__(256) void prep_w(
    const float* __restrict__ Wq, const float* __restrict__ Wk,
    const float* __restrict__ Wv, const float* __restrict__ Wo)
{
    int i = blockIdx.x * 256 + threadIdx.x;
    int w = i >> 16, off = i & 65535;
    const float* src; __half* dst; float scale = 1.f;
    if      (w == 0) { src = Wq; dst = g_Wqh; scale = 0.125f; }
    else if (w == 1) { src = Wk; dst = g_Wkh; }
    else if (w == 2) { src = Wv; dst = g_Wvh; }
    else             { src = Wo; dst = g_Woh; }
    float4 v = reinterpret_cast<const float4*>(src)[off];
    v.x *= scale; v.y *= scale; v.z *= scale; v.w *= scale;
    reinterpret_cast<uint2*>(dst)[off] = pack4(v);
}

// ---------------------------------------------------------------------------
// fused kernel: one block per batch element, 256 threads, warp = head.
// ---------------------------------------------------------------------------
__global__ __launch_bounds__(256, 1) void fused_kernel(
    const float* __restrict__ x, const float* __restrict__ l,
    const float* __restrict__ bo, float* __restrict__ out)
{
    extern __shared__ __half sm[];
    __half* x_s = sm + XS_OFF;     // [16][520]  (reused as ov_s in P5)
    __half* l_s = sm + LS_OFF;     // [128][520]
    __half* s_s = sm + SS_OFF;     // [128][136]
    __half* w_s = sm + WS_OFF;     // [512][40]  weight chunk [row][32 cols]

    const int b = blockIdx.x;
    const int m = b & (NLAT - 1);
    const int njt = (m >> 5) + 1;
    const int rows = njt << 5;

    const int tid = threadIdx.x;
    const int h = tid >> 5, lane = tid & 31;
    const int g = lane >> 2, t = lane & 3;
    const int l15 = lane & 15, lhi = (lane >> 4) * 8;

    // stage one weight chunk: w_s[r][c] = W[r][c0+c], 512 rows x 32 cols
    auto stageW = [&](const __half* W, int c0) {
#pragma unroll
        for (int it = 0; it < 8; it++) {
            int idx = tid + it * 256;
            int r = idx >> 2, s4 = idx & 3;
            cp16(sm_u32(w_s + r * 40 + s4 * 8), W + r * DIM + c0 + s4 * 8);
        }
        asm volatile("cp.async.commit_group;");
    };

    stageW(g_Wqh, 0);   // first Wq chunk flies during x/l staging

    // ---- P0: stage x_s (fp32 -> fp16) and l_s (masked rows, once) ----
#pragma unroll
    for (int it = 0; it < 8; it++) {
        int idx = tid + it * 256;
        int r = idx >> 7, c4 = idx & 127;
        float4 v = *reinterpret_cast<const float4*>(
            x + ((size_t)b * NTOK + r) * DIM + c4 * 4);
        *reinterpret_cast<uint2*>(x_s + r * 520 + c4 * 4) = pack4(v);
    }
    const float* lb = l + (size_t)b * NLAT * DIM;
    const int lit = rows >> 1;
#pragma unroll 4
    for (int it = 0; it < lit; it++) {
        int idx = tid + it * 256;
        int r = idx >> 7, c4 = idx & 127;
        uint2 z = make_uint2(0u, 0u);
        if (r <= m) {
            float4 v = *reinterpret_cast<const float4*>(
                lb + (size_t)r * DIM + c4 * 4);
            z = pack4(v);
        }
        *reinterpret_cast<uint2*>(l_s + r * 520 + c4 * 4) = z;
    }
    __syncthreads();

    const uint32_t xs_base = sm_u32(x_s) + (uint32_t)(l15 * 520 + lhi) * 2;
    const uint32_t ls_base = sm_u32(l_s) + (uint32_t)(l15 * 520 + lhi) * 2;
    const uint32_t ws_base = sm_u32(w_s) + (uint32_t)((h * 64 + l15) * 40 + lhi) * 2;
    const uint32_t ss_base = sm_u32(s_s) + (uint32_t)((h * 16 + l15) * 136 + lhi) * 2;

    // ---- P1: q_h = x @ Wq_h^T  (accumulate cqq over 16 k-chunks) ----
    float cqq[8][4];
#pragma unroll
    for (int f = 0; f < 8; f++)
#pragma unroll
        for (int e = 0; e < 4; e++) cqq[f][e] = 0.f;

    for (int ec = 0; ec < 16; ec++) {
        asm volatile("cp.async.wait_group 0;");
        __syncthreads();
#pragma unroll
        for (int kk = 0; kk < 2; kk++) {
            uint32_t a0, a1, a2, a3;
            ldsm_x4(a0, a1, a2, a3, xs_base + (ec * 32 + kk * 16) * 2);
#pragma unroll
            for (int dn = 0; dn < 4; dn++) {
                uint32_t b0, b1, b2, b3;
                ldsm_x4(b0, b1, b2, b3, ws_base + (dn * 16 * 40 + kk * 16) * 2);
                mma_fp16(cqq[2 * dn],     a0, a1, a2, a3, b0, b2);
                mma_fp16(cqq[2 * dn + 1], a0, a1, a2, a3, b1, b3);
            }
        }
        __syncthreads();
        if (ec < 15) stageW(g_Wqh, (ec + 1) * 32);
        else         stageW(g_Wkh, 0);
    }
    // pack q into A-fragments (k = d, 4 k16 steps)
    uint32_t aq[4][4];
#pragma unroll
    for (int dk = 0; dk < 4; dk++)
        packA(cqq[2 * dk], cqq[2 * dk + 1],
              aq[dk][0], aq[dk][1], aq[dk][2], aq[dk][3]);

    // ---- P2: qk chunk = q_h @ Wk_h ; scores += qk @ l^T ----
    float cs[16][4];
#pragma unroll
    for (int f = 0; f < 16; f++)
#pragma unroll
        for (int e = 0; e < 4; e++) cs[f][e] = 0.f;

    for (int ec = 0; ec < 16; ec++) {
        asm volatile("cp.async.wait_group 0;");
        __syncthreads();
        float cq[4][4];
#pragma unroll
        for (int f = 0; f < 4; f++)
#pragma unroll
            for (int e = 0; e < 4; e++) cq[f][e] = 0.f;
#pragma unroll
        for (int dk = 0; dk < 4; dk++) {
#pragma unroll
            for (int ep = 0; ep < 2; ep++) {
                uint32_t b0, b1, b2, b3;
                ldsm_x4t(b0, b1, b2, b3, ws_base + (dk * 16 * 40 + ep * 16) * 2);
                mma_fp16(cq[2 * ep],     aq[dk][0], aq[dk][1], aq[dk][2], aq[dk][3], b0, b1);
                mma_fp16(cq[2 * ep + 1], aq[dk][0], aq[dk][1], aq[dk][2], aq[dk][3], b2, b3);
            }
        }
        __syncthreads();
        if (ec < 15) stageW(g_Wkh, (ec + 1) * 32);
        else         stageW(g_Wvh, 0);
        // scores (overlaps the prefetch above)
#pragma unroll
        for (int kk = 0; kk < 2; kk++) {
            uint32_t a0, a1, a2, a3;
            packA(cq[2 * kk], cq[2 * kk + 1], a0, a1, a2, a3);
#pragma unroll
            for (int jt = 0; jt < 4; jt++) {
                if (jt < njt) {
#pragma unroll
                    for (int jp = 0; jp < 2; jp++) {
                        uint32_t b0, b1, b2, b3;
                        ldsm_x4(b0, b1, b2, b3,
                                ls_base + ((jt * 32 + jp * 16) * 520 + ec * 32 + kk * 16) * 2);
                        mma_fp16(cs[jt * 4 + jp * 2],     a0, a1, a2, a3, b0, b2);
                        mma_fp16(cs[jt * 4 + jp * 2 + 1], a0, a1, a2, a3, b1, b3);
                    }
                }
            }
        }
    }

    // ---- P3: masked softmax (rows g, g+8 per thread) -> s_s ----
    float mx0 = -1e30f, mx1 = -1e30f;
#pragma unroll
    for (int f = 0; f < 16; f++) {
        const int jb = f * 8 + 2 * t;
#pragma unroll
        for (int e = 0; e < 2; e++) {
            if (jb + e > m) { cs[f][e] = -1e30f; cs[f][2 + e] = -1e30f; }
            mx0 = fmaxf(mx0, cs[f][e]);
            mx1 = fmaxf(mx1, cs[f][2 + e]);
        }
    }
    mx0 = fmaxf(mx0, __shfl_xor_sync(0xffffffffu, mx0, 1));
    mx0 = fmaxf(mx0, __shfl_xor_sync(0xffffffffu, mx0, 2));
    mx1 = fmaxf(mx1, __shfl_xor_sync(0xffffffffu, mx1, 1));
    mx1 = fmaxf(mx1, __shfl_xor_sync(0xffffffffu, mx1, 2));
    float s0 = 0.f, s1 = 0.f;
#pragma unroll
    for (int f = 0; f < 16; f++)
#pragma unroll
        for (int e = 0; e < 2; e++) {
            cs[f][e] = __expf(cs[f][e] - mx0);         s0 += cs[f][e];
            cs[f][2 + e] = __expf(cs[f][2 + e] - mx1); s1 += cs[f][2 + e];
        }
    s0 += __shfl_xor_sync(0xffffffffu, s0, 1);
    s0 += __shfl_xor_sync(0xffffffffu, s0, 2);
    s1 += __shfl_xor_sync(0xffffffffu, s1, 1);
    s1 += __shfl_xor_sync(0xffffffffu, s1, 2);
    const float i0 = 1.f / s0, i1 = 1.f / s1;
#pragma unroll
    for (int f = 0; f < 16; f++) {
        const int jb = f * 8 + 2 * t;
        *reinterpret_cast<uint32_t*>(s_s + (h * 16 + g) * 136 + jb) =
            packh2(cs[f][0] * i0, cs[f][1] * i0);
        *reinterpret_cast<uint32_t*>(s_s + (h * 16 + g + 8) * 136 + jb) =
            packh2(cs[f][2] * i1, cs[f][3] * i1);
    }
    __syncwarp();   // s_s rows are warp-private

    // ---- P4: AL chunk = attn @ l ; OV += AL @ Wv_h^T ----
    float cov[8][4];
#pragma unroll
    for (int f = 0; f < 8; f++)
#pragma unroll
        for (int e = 0; e < 4; e++) cov[f][e] = 0.f;

    for (int ec = 0; ec < 16; ec++) {
        float cal[4][4];
#pragma unroll
        for (int f = 0; f < 4; f++)
#pragma unroll
            for (int e = 0; e < 4; e++) cal[f][e] = 0.f;
        // AL: A = s_s (k=j), B = l_s trans (n=e)  — no w_s use, overlaps prefetch
        for (int jk = 0; jk < njt * 2; jk++) {
            uint32_t a0, a1, a2, a3;
            ldsm_x4(a0, a1, a2, a3, ss_base + (jk * 16) * 2);
#pragma unroll
            for (int ep = 0; ep < 2; ep++) {
                uint32_t b0, b1, b2, b3;
                ldsm_x4t(b0, b1, b2, b3,
                         ls_base + ((jk * 16) * 520 + ec * 32 + ep * 16) * 2);
                mma_fp16(cal[2 * ep],     a0, a1, a2, a3, b0, b1);
                mma_fp16(cal[2 * ep + 1], a0, a1, a2, a3, b2, b3);
            }
        }
        asm volatile("cp.async.wait_group 0;");
        __syncthreads();
        // OV accumulate: A = packed AL (k=e), B = w_s (Wv, n=d)
#pragma unroll
        for (int kk = 0; kk < 2; kk++) {
            uint32_t a0, a1, a2, a3;
            packA(cal[2 * kk], cal[2 * kk + 1], a0, a1, a2, a3);
#pragma unroll
            for (int dn = 0; dn < 4; dn++) {
                uint32_t b0, b1, b2, b3;
                ldsm_x4(b0, b1, b2, b3, ws_base + (dn * 16 * 40 + kk * 16) * 2);
                mma_fp16(cov[2 * dn],     a0, a1, a2, a3, b0, b2);
                mma_fp16(cov[2 * dn + 1], a0, a1, a2, a3, b1, b3);
            }
        }
        __syncthreads();
        if (ec < 15) stageW(g_Wvh, (ec + 1) * 32);
        else         stageW(g_Woh, 0);
    }

    // ---- P5: cov -> ov_s (x_s reuse); out = OV @ Wo^T + bo ----
#pragma unroll
    for (int f = 0; f < 8; f++) {
        const int col = h * 64 + f * 8 + 2 * t;
        *reinterpret_cast<uint32_t*>(x_s + g * 520 + col) =
            packh2(cov[f][0], cov[f][1]);
        *reinterpret_cast<uint32_t*>(x_s + (g + 8) * 520 + col) =
            packh2(cov[f][2], cov[f][3]);
    }
    float cfin[8][4];
#pragma unroll
    for (int f = 0; f < 8; f++)
#pragma unroll
        for (int e = 0; e < 4; e++) cfin[f][e] = 0.f;

    for (int ec = 0; ec < 16; ec++) {
        asm volatile("cp.async.wait_group 0;");
        __syncthreads();    // also makes ov_s writes visible at ec=0
#pragma unroll
        for (int kk = 0; kk < 2; kk++) {
            uint32_t a0, a1, a2, a3;
            ldsm_x4(a0, a1, a2, a3, xs_base + (ec * 32 + kk * 16) * 2);
#pragma unroll
            for (int dn = 0; dn < 4; dn++) {
                uint32_t b0, b1, b2, b3;
                ldsm_x4(b0, b1, b2, b3, ws_base + (dn * 16 * 40 + kk * 16) * 2);
                mma_fp16(cfin[2 * dn],     a0, a1, a2, a3, b0, b2);
                mma_fp16(cfin[2 * dn + 1], a0, a1, a2, a3, b1, b3);
            }
        }
        __syncthreads();
        if (ec < 15) stageW(g_Woh, (ec + 1) * 32);
    }
#pragma unroll
    for (int f = 0; f < 8; f++) {
        const int col = h * 64 + f * 8 + 2 * t;
        float b0v = bo[col], b1v = bo[col + 1];
        *reinterpret_cast<float2*>(out + ((size_t)b * NTOK + g) * DIM + col) =
            make_float2(cfin[f][0] + b0v, cfin[f][1] + b1v);
        *reinterpret_cast<float2*>(out + ((size_t)b * NTOK + g + 8) * DIM + col) =
            make_float2(cfin[f][2] + b0v, cfin[f][3] + b1v);
    }
}

// ---------------------------------------------------------------------------
extern "C" void kernel_launch(void* const* d_in, const int* in_sizes, int n_in,
                              void* d_out, int out_size)
{
    const float* x  = (const float*)d_in[0];
    const float* l  = (const float*)d_in[1];
    const float* Wq = (const float*)d_in[2];
    const float* Wk = (const float*)d_in[3];
    const float* Wv = (const float*)d_in[4];
    const float* Wo = (const float*)d_in[5];
    const float* bo = (const float*)d_in[6];
    float* out = (float*)d_out;

    cudaFuncSetAttribute(fused_kernel,
                         cudaFuncAttributeMaxDynamicSharedMemorySize, SMEM_B);

    prep_w<<<1024, 256>>>(Wq, Wk, Wv, Wo);          // 4 x 64K float4
    fused_kernel<<<NB, 256, SMEM_B>>>(x, l, bo, out);
}